// round 1
// baseline (speedup 1.0000x reference)
#include <cuda_runtime.h>
#include <math.h>
#include <stdint.h>

// Problem constants
namespace {
constexpr int B_ = 256;
constexpr int S_ = 128;
constexpr int H_ = 512;
constexpr int E_ = 512;
constexpr int V_ = 32000;
constexpr int IN_ = E_ + 2 * H_;   // 1536
constexpr int G_ = 3 * H_;         // 1536
}

// Scratch (static device globals — no allocation at kernel_launch time)
__device__ float g_x[B_ * IN_];        // [B, E+2H]
__device__ float g_gi[B_ * G_];        // [B, 3H]
__device__ float g_gh[B_ * G_];        // [B, 3H]
__device__ float g_hidden[B_ * H_];    // [B, H]
__device__ float g_sc[B_ * S_];        // [B, S] einsum(score_c, hidden)
__device__ float g_attn[B_ * S_];      // [B, S]

// ---------------------------------------------------------------------------
// build x = concat(embed_w[input_ids], weighted)
// ---------------------------------------------------------------------------
__global__ void build_x_kernel(const int* __restrict__ ids,
                               const float* __restrict__ emb,
                               const float* __restrict__ weighted) {
    int idx = blockIdx.x * blockDim.x + threadIdx.x;   // < B*IN
    int b = idx / IN_;
    int j = idx - b * IN_;
    float v;
    if (j < E_) {
        v = emb[(size_t)ids[b] * E_ + j];
    } else {
        v = weighted[b * (2 * H_) + (j - E_)];
    }
    g_x[idx] = v;
}

__global__ void zero_sc_kernel() {
    int idx = blockIdx.x * blockDim.x + threadIdx.x;   // < B*S
    g_sc[idx] = 0.f;
}

// ---------------------------------------------------------------------------
// Tiled SGEMM: C[M,N] = A[M,K] @ Bw[N,K]^T + bias[N]
// MODE 0: write C (with bias)
// MODE 1: fused score_c epilogue:
//         val = tanh(acc + bias[n]); sc[m] += val * hidden[(m>>7)*H + n]
//         (C unused; scOut = g_sc, accumulated with atomics)
// Requirements (all satisfied here): M%128==0, N%64==0, K%16==0.
// ---------------------------------------------------------------------------
constexpr int BM = 128, BN = 64, BK = 16, TM = 8, TN = 4;

template <int MODE>
__global__ void __launch_bounds__(256)
sgemm_kernel(const float* __restrict__ A, const float* __restrict__ Bw,
             const float* __restrict__ bias, float* __restrict__ C,
             int M, int N, int K,
             const float* __restrict__ hidden, float* __restrict__ scOut) {
    __shared__ float As[BK][BM];
    __shared__ float Bs[BK][BN];

    const int t = threadIdx.x;
    const int tx = t & 15;       // 0..15 -> N dir (TN=4 -> 64)
    const int ty = t >> 4;       // 0..15 -> M dir (TM=8 -> 128)
    const int m0 = blockIdx.y * BM;
    const int n0 = blockIdx.x * BN;

    float acc[TM][TN];
#pragma unroll
    for (int i = 0; i < TM; i++)
#pragma unroll
        for (int j = 0; j < TN; j++) acc[i][j] = 0.f;

    for (int k0 = 0; k0 < K; k0 += BK) {
        // Load A tile: 128x16 = 512 float4, 2 per thread
#pragma unroll
        for (int l = 0; l < 2; l++) {
            int e = t + l * 256;
            int i = e >> 2;
            int kq = e & 3;
            float4 v = *reinterpret_cast<const float4*>(
                &A[(size_t)(m0 + i) * K + k0 + kq * 4]);
            As[kq * 4 + 0][i] = v.x;
            As[kq * 4 + 1][i] = v.y;
            As[kq * 4 + 2][i] = v.z;
            As[kq * 4 + 3][i] = v.w;
        }
        // Load B tile: 64x16 = 256 float4, 1 per thread
        {
            int i = t >> 2;
            int kq = t & 3;
            float4 v = *reinterpret_cast<const float4*>(
                &Bw[(size_t)(n0 + i) * K + k0 + kq * 4]);
            Bs[kq * 4 + 0][i] = v.x;
            Bs[kq * 4 + 1][i] = v.y;
            Bs[kq * 4 + 2][i] = v.z;
            Bs[kq * 4 + 3][i] = v.w;
        }
        __syncthreads();

#pragma unroll
        for (int k = 0; k < BK; k++) {
            float a[TM], bb[TN];
            float4 a0 = *reinterpret_cast<const float4*>(&As[k][ty * TM]);
            float4 a1 = *reinterpret_cast<const float4*>(&As[k][ty * TM + 4]);
            a[0] = a0.x; a[1] = a0.y; a[2] = a0.z; a[3] = a0.w;
            a[4] = a1.x; a[5] = a1.y; a[6] = a1.z; a[7] = a1.w;
            float4 b0 = *reinterpret_cast<const float4*>(&Bs[k][tx * TN]);
            bb[0] = b0.x; bb[1] = b0.y; bb[2] = b0.z; bb[3] = b0.w;
#pragma unroll
            for (int i = 0; i < TM; i++)
#pragma unroll
                for (int j = 0; j < TN; j++) acc[i][j] = fmaf(a[i], bb[j], acc[i][j]);
        }
        __syncthreads();
    }

    if (MODE == 0) {
        float bz[TN];
#pragma unroll
        for (int j = 0; j < TN; j++) bz[j] = bias[n0 + tx * TN + j];
#pragma unroll
        for (int i = 0; i < TM; i++) {
            int m = m0 + ty * TM + i;
            float4 o;
            o.x = acc[i][0] + bz[0];
            o.y = acc[i][1] + bz[1];
            o.z = acc[i][2] + bz[2];
            o.w = acc[i][3] + bz[3];
            *reinterpret_cast<float4*>(&C[(size_t)m * N + n0 + tx * TN]) = o;
        }
    } else {
        // fused score_c epilogue
        float bz[TN], hv[TN];
        int bidx = (m0 >> 7);  // all rows in this block share b (BM == S_ == 128)
#pragma unroll
        for (int j = 0; j < TN; j++) {
            int n = n0 + tx * TN + j;
            bz[j] = bias[n];
            hv[j] = hidden[bidx * H_ + n];
        }
        float part[TM];
#pragma unroll
        for (int i = 0; i < TM; i++) {
            float p = 0.f;
#pragma unroll
            for (int j = 0; j < TN; j++) {
                float v = tanhf(acc[i][j] + bz[j]);
                p = fmaf(v, hv[j], p);
            }
            part[i] = p;
        }
        // reduce across the 16 tx lanes (contiguous half-warps)
#pragma unroll
        for (int off = 8; off >= 1; off >>= 1) {
#pragma unroll
            for (int i = 0; i < TM; i++)
                part[i] += __shfl_down_sync(0xffffffffu, part[i], off);
        }
        if (tx == 0) {
#pragma unroll
            for (int i = 0; i < TM; i++)
                atomicAdd(&scOut[m0 + ty * TM + i], part[i]);
        }
    }
}

// ---------------------------------------------------------------------------
// GRU gates (order==1 path; prev_state/weighted come from inputs)
// ---------------------------------------------------------------------------
__global__ void gru_kernel(const float* __restrict__ prev,
                           float* __restrict__ outHidden) {
    int idx = blockIdx.x * blockDim.x + threadIdx.x;   // < B*H
    int b = idx >> 9;
    int h = idx & (H_ - 1);
    const float* gi = g_gi + (size_t)b * G_;
    const float* gh = g_gh + (size_t)b * G_;
    float ir = gi[h], iz = gi[h + H_], inn = gi[h + 2 * H_];
    float hr = gh[h], hz = gh[h + H_], hn = gh[h + 2 * H_];
    float r = 1.f / (1.f + expf(-(ir + hr)));
    float z = 1.f / (1.f + expf(-(iz + hz)));
    float n = tanhf(inn + r * hn);
    float hv = (1.f - z) * n + z * prev[idx];
    g_hidden[idx] = hv;
    outHidden[idx] = hv;
}

// ---------------------------------------------------------------------------
// Per-row softmax over [score_g(32000) | tanh(sc + mask)(128)], scatter-add
// prob_c at src positions, compute attn weights.
// pred row already contains score_g logits; normalized in place.
// ---------------------------------------------------------------------------
__global__ void __launch_bounds__(512)
softmax_kernel(float* __restrict__ pred, const int* __restrict__ src,
               const int* __restrict__ ids) {
    __shared__ float s_lc[S_];
    __shared__ float s_red[512];
    __shared__ int s_cnt;
    const int b = blockIdx.x;
    const int t = threadIdx.x;
    float* row = pred + (size_t)b * V_;

    if (t == 0) s_cnt = 0;
    if (t < S_) {
        float mask = (src[b * S_ + t] == 0) ? -1000.f : 0.f;
        s_lc[t] = tanhf(g_sc[b * S_ + t] + mask);
    }
    __syncthreads();

    // max
    float lmax = -1e30f;
    for (int v = t; v < V_; v += 512) lmax = fmaxf(lmax, row[v]);
    if (t < S_) lmax = fmaxf(lmax, s_lc[t]);
    s_red[t] = lmax;
    __syncthreads();
    for (int o = 256; o; o >>= 1) {
        if (t < o) s_red[t] = fmaxf(s_red[t], s_red[t + o]);
        __syncthreads();
    }
    float gmax = s_red[0];
    __syncthreads();

    // sum exp
    float lsum = 0.f;
    for (int v = t; v < V_; v += 512) lsum += expf(row[v] - gmax);
    if (t < S_) lsum += expf(s_lc[t] - gmax);
    s_red[t] = lsum;
    __syncthreads();
    for (int o = 256; o; o >>= 1) {
        if (t < o) s_red[t] += s_red[t + o];
        __syncthreads();
    }
    float inv = 1.f / s_red[0];

    // write prob_g
    for (int v = t; v < V_; v += 512) row[v] = expf(row[v] - gmax) * inv;

    // count matches (eq.sum)
    int id = ids[b];
    if (t < S_ && src[b * S_ + t] == id) atomicAdd(&s_cnt, 1);
    __syncthreads();  // prob_g writes visible; count final

    if (t < S_) {
        float pc = expf(s_lc[t] - gmax) * inv;
        atomicAdd(&row[src[b * S_ + t]], pc);   // prob_c_to_g scatter-add
        float eq = (src[b * S_ + t] == id) ? 1.f : 0.f;
        g_attn[b * S_ + t] = pc * eq / fmaxf((float)s_cnt, 1.f);
    }
}

// ---------------------------------------------------------------------------
// weighted_out[b,d] = sum_s attn[b,s] * encoded[b,s,d]
// ---------------------------------------------------------------------------
__global__ void __launch_bounds__(256)
weighted_kernel(const float* __restrict__ enc, float* __restrict__ outW) {
    __shared__ float s_a[S_];
    const int b = blockIdx.x;
    const int t = threadIdx.x;
    if (t < S_) s_a[t] = g_attn[b * S_ + t];
    __syncthreads();
    float4 acc = make_float4(0.f, 0.f, 0.f, 0.f);
    const float4* e4 =
        reinterpret_cast<const float4*>(enc + (size_t)b * S_ * (2 * H_));
    for (int s = 0; s < S_; s++) {
        float w = s_a[s];
        if (w != 0.f) {   // uniform branch; matches are rare
            float4 e = e4[s * 256 + t];
            acc.x = fmaf(w, e.x, acc.x);
            acc.y = fmaf(w, e.y, acc.y);
            acc.z = fmaf(w, e.z, acc.z);
            acc.w = fmaf(w, e.w, acc.w);
        }
    }
    reinterpret_cast<float4*>(outW)[b * 256 + t] = acc;
}

// ---------------------------------------------------------------------------
extern "C" void kernel_launch(void* const* d_in, const int* in_sizes, int n_in,
                              void* d_out, int out_size) {
    const int*   input_ids = (const int*)d_in[0];
    const float* encoded   = (const float*)d_in[1];
    const int*   src       = (const int*)d_in[2];
    const float* prev      = (const float*)d_in[3];
    const float* weighted  = (const float*)d_in[4];
    // d_in[5] = order (always 1 for this problem's inputs)
    const float* embed_w   = (const float*)d_in[6];
    const float* w_ih      = (const float*)d_in[7];
    const float* w_hh      = (const float*)d_in[8];
    const float* b_ih      = (const float*)d_in[9];
    const float* b_hh      = (const float*)d_in[10];
    const float* Wo_w      = (const float*)d_in[13];
    const float* Wo_b      = (const float*)d_in[14];
    const float* Wc_w      = (const float*)d_in[15];
    const float* Wc_b      = (const float*)d_in[16];

    float* pred        = (float*)d_out;                       // [B,1,V]
    float* outHidden   = pred + (size_t)B_ * V_;              // [B,H]
    float* outWeighted = outHidden + (size_t)B_ * H_;         // [B,2H]

    float *px, *pgi, *pgh, *phid, *psc;
    cudaGetSymbolAddress((void**)&px,   g_x);
    cudaGetSymbolAddress((void**)&pgi,  g_gi);
    cudaGetSymbolAddress((void**)&pgh,  g_gh);
    cudaGetSymbolAddress((void**)&phid, g_hidden);
    cudaGetSymbolAddress((void**)&psc,  g_sc);

    // 1) x = concat(embed[ids], weighted)
    build_x_kernel<<<(B_ * IN_) / 256, 256>>>(input_ids, embed_w, weighted);

    // 2) gi = x @ W_ih^T + b_ih     (M=256, N=1536, K=1536)
    sgemm_kernel<0><<<dim3(IN_ / BN, B_ / BM), 256>>>(
        px, w_ih, b_ih, pgi, B_, G_, IN_, nullptr, nullptr);

    // 3) gh = prev @ W_hh^T + b_hh  (M=256, N=1536, K=512)
    sgemm_kernel<0><<<dim3(G_ / BN, B_ / BM), 256>>>(
        prev, w_hh, b_hh, pgh, B_, G_, H_, nullptr, nullptr);

    // 4) GRU gates -> hidden
    gru_kernel<<<(B_ * H_) / 256, 256>>>(prev, outHidden);

    // 5) score_g = hidden @ Wo^T + Wo_b -> pred (logits in place)
    sgemm_kernel<0><<<dim3(V_ / BN, B_ / BM), 256>>>(
        phid, Wo_w, Wo_b, pred, B_, V_, H_, nullptr, nullptr);

    // 6) sc[b,s] = sum_h tanh(enc @ Wc^T + Wc_b) * hidden  (fused epilogue)
    zero_sc_kernel<<<(B_ * S_) / 256, 256>>>();
    sgemm_kernel<1><<<dim3(H_ / BN, (B_ * S_) / BM), 256>>>(
        encoded, Wc_w, Wc_b, nullptr, B_ * S_, H_, 2 * H_, phid, psc);

    // 7) softmax over [score_g | tanh(sc+mask)], scatter, attn
    softmax_kernel<<<B_, 512>>>(pred, src, input_ids);

    // 8) weighted_out = attn @ encoded
    weighted_kernel<<<B_, 256>>>(encoded, outWeighted);

    (void)in_sizes; (void)n_in; (void)out_size;
}

// round 3
// speedup vs baseline: 1.8928x; 1.8928x over previous
#include <cuda_runtime.h>
#include <cuda_bf16.h>
#include <math.h>
#include <stdint.h>

namespace {
constexpr int B_ = 256;
constexpr int S_ = 128;
constexpr int H_ = 512;
constexpr int E_ = 512;
constexpr int V_ = 32000;
constexpr int IN_ = E_ + 2 * H_;   // 1536
constexpr int G_ = 3 * H_;         // 1536
}

// ---------------- static scratch ----------------
__device__ float g_x[B_ * IN_];
__device__ float g_gi[B_ * G_];
__device__ float g_gh[B_ * G_];
__device__ float g_hidden[B_ * H_];
__device__ float g_sc[B_ * S_];
__device__ float g_attn[B_ * S_];

__device__ __nv_bfloat16 g_enc_hi[B_ * S_ * 2 * H_];
__device__ __nv_bfloat16 g_enc_lo[B_ * S_ * 2 * H_];
__device__ __nv_bfloat16 g_wo_hi[V_ * H_];
__device__ __nv_bfloat16 g_wo_lo[V_ * H_];
__device__ __nv_bfloat16 g_wc_hi[H_ * 2 * H_];
__device__ __nv_bfloat16 g_wc_lo[H_ * 2 * H_];
__device__ __nv_bfloat16 g_hid_hi[B_ * H_];
__device__ __nv_bfloat16 g_hid_lo[B_ * H_];

// ---------------- helpers ----------------
__device__ __forceinline__ uint32_t smem_u32(const void* p) {
    uint32_t a;
    asm("{ .reg .u64 t; cvta.to.shared.u64 t, %1; cvt.u32.u64 %0, t; }"
        : "=r"(a) : "l"(p));
    return a;
}

__device__ __forceinline__ void cp_async16(uint32_t s, const void* g) {
    asm volatile("cp.async.cg.shared.global [%0], [%1], 16;\n"
                 :: "r"(s), "l"(g) : "memory");
}
__device__ __forceinline__ void cp_commit() {
    asm volatile("cp.async.commit_group;\n" ::: "memory");
}
template <int N>
__device__ __forceinline__ void cp_wait() {
    asm volatile("cp.async.wait_group %0;\n" :: "n"(N) : "memory");
}

__device__ __forceinline__ void ldmx4(uint32_t& r0, uint32_t& r1, uint32_t& r2,
                                      uint32_t& r3, uint32_t addr) {
    asm volatile("ldmatrix.sync.aligned.m8n8.x4.shared.b16 {%0,%1,%2,%3}, [%4];\n"
                 : "=r"(r0), "=r"(r1), "=r"(r2), "=r"(r3) : "r"(addr));
}

__device__ __forceinline__ void mma16816(float* d, const uint32_t* a,
                                         const uint32_t* b) {
    asm volatile(
        "mma.sync.aligned.m16n8k16.row.col.f32.bf16.bf16.f32 "
        "{%0,%1,%2,%3}, {%4,%5,%6,%7}, {%8,%9}, {%0,%1,%2,%3};\n"
        : "+f"(d[0]), "+f"(d[1]), "+f"(d[2]), "+f"(d[3])
        : "r"(a[0]), "r"(a[1]), "r"(a[2]), "r"(a[3]), "r"(b[0]), "r"(b[1]));
}

// ---------------- elementwise kernels ----------------
__global__ void build_x_kernel(const int* __restrict__ ids,
                               const float* __restrict__ emb,
                               const float* __restrict__ weighted) {
    int idx = blockIdx.x * blockDim.x + threadIdx.x;
    int b = idx / IN_;
    int j = idx - b * IN_;
    float v = (j < E_) ? emb[(size_t)ids[b] * E_ + j]
                       : weighted[b * (2 * H_) + (j - E_)];
    g_x[idx] = v;
}

__global__ void zero_sc_kernel() {
    int idx = blockIdx.x * blockDim.x + threadIdx.x;
    g_sc[idx] = 0.f;
}

__global__ void split_kernel(const float* __restrict__ s,
                             __nv_bfloat16* __restrict__ hi,
                             __nv_bfloat16* __restrict__ lo, int n) {
    int i = (blockIdx.x * blockDim.x + threadIdx.x) * 4;
    if (i >= n) return;
    float4 v = *reinterpret_cast<const float4*>(s + i);
    __nv_bfloat16 h0 = __float2bfloat16(v.x);
    __nv_bfloat16 h1 = __float2bfloat16(v.y);
    __nv_bfloat16 h2 = __float2bfloat16(v.z);
    __nv_bfloat16 h3 = __float2bfloat16(v.w);
    __nv_bfloat16 l0 = __float2bfloat16(v.x - __bfloat162float(h0));
    __nv_bfloat16 l1 = __float2bfloat16(v.y - __bfloat162float(h1));
    __nv_bfloat16 l2 = __float2bfloat16(v.z - __bfloat162float(h2));
    __nv_bfloat16 l3 = __float2bfloat16(v.w - __bfloat162float(h3));
    reinterpret_cast<__nv_bfloat162*>(hi + i)[0] = __nv_bfloat162(h0, h1);
    reinterpret_cast<__nv_bfloat162*>(hi + i)[1] = __nv_bfloat162(h2, h3);
    reinterpret_cast<__nv_bfloat162*>(lo + i)[0] = __nv_bfloat162(l0, l1);
    reinterpret_cast<__nv_bfloat162*>(lo + i)[1] = __nv_bfloat162(l2, l3);
}

// ---------------- fp32 SGEMM (gi/gh) ----------------
constexpr int BMr = 128, BNr = 64, BKr = 16, TMr = 8, TNr = 4;

__global__ void __launch_bounds__(256)
sgemm_kernel(const float* __restrict__ A, const float* __restrict__ Bw,
             const float* __restrict__ bias, float* __restrict__ C,
             int M, int N, int K) {
    __shared__ float As[BKr][BMr];
    __shared__ float Bs[BKr][BNr];
    const int t = threadIdx.x;
    const int tx = t & 15, ty = t >> 4;
    const int m0 = blockIdx.y * BMr, n0 = blockIdx.x * BNr;
    float acc[TMr][TNr];
#pragma unroll
    for (int i = 0; i < TMr; i++)
#pragma unroll
        for (int j = 0; j < TNr; j++) acc[i][j] = 0.f;

    for (int k0 = 0; k0 < K; k0 += BKr) {
#pragma unroll
        for (int l = 0; l < 2; l++) {
            int e = t + l * 256, i = e >> 2, kq = e & 3;
            float4 v = *reinterpret_cast<const float4*>(&A[(size_t)(m0 + i) * K + k0 + kq * 4]);
            As[kq * 4 + 0][i] = v.x; As[kq * 4 + 1][i] = v.y;
            As[kq * 4 + 2][i] = v.z; As[kq * 4 + 3][i] = v.w;
        }
        {
            int i = t >> 2, kq = t & 3;
            float4 v = *reinterpret_cast<const float4*>(&Bw[(size_t)(n0 + i) * K + k0 + kq * 4]);
            Bs[kq * 4 + 0][i] = v.x; Bs[kq * 4 + 1][i] = v.y;
            Bs[kq * 4 + 2][i] = v.z; Bs[kq * 4 + 3][i] = v.w;
        }
        __syncthreads();
#pragma unroll
        for (int k = 0; k < BKr; k++) {
            float a[TMr], bb[TNr];
            float4 a0 = *reinterpret_cast<const float4*>(&As[k][ty * TMr]);
            float4 a1 = *reinterpret_cast<const float4*>(&As[k][ty * TMr + 4]);
            a[0] = a0.x; a[1] = a0.y; a[2] = a0.z; a[3] = a0.w;
            a[4] = a1.x; a[5] = a1.y; a[6] = a1.z; a[7] = a1.w;
            float4 b0 = *reinterpret_cast<const float4*>(&Bs[k][tx * TNr]);
            bb[0] = b0.x; bb[1] = b0.y; bb[2] = b0.z; bb[3] = b0.w;
#pragma unroll
            for (int i = 0; i < TMr; i++)
#pragma unroll
                for (int j = 0; j < TNr; j++) acc[i][j] = fmaf(a[i], bb[j], acc[i][j]);
        }
        __syncthreads();
    }
    float bz[TNr];
#pragma unroll
    for (int j = 0; j < TNr; j++) bz[j] = bias[n0 + tx * TNr + j];
#pragma unroll
    for (int i = 0; i < TMr; i++) {
        int m = m0 + ty * TMr + i;
        float4 o;
        o.x = acc[i][0] + bz[0]; o.y = acc[i][1] + bz[1];
        o.z = acc[i][2] + bz[2]; o.w = acc[i][3] + bz[3];
        *reinterpret_cast<float4*>(&C[(size_t)m * N + n0 + tx * TNr]) = o;
    }
}

// ---------------- mma.sync bf16 split GEMM ----------------
// C[M,N] = A[M,K] @ W[N,K]^T via 3-pass bf16 split (hi*hi + lo*hi + hi*lo)
// MODE 0: C[m,n] = acc + bias[n]
// MODE 1: sc[m] += sum_n tanh(acc + bias[n]) * hidden[m>>7, n]
constexpr int GM = 128, GN = 128, GK = 32;
constexpr int ROWB = 80;                 // padded row stride (bytes) for 64B rows
constexpr int TILEB = 128 * ROWB;        // 10240 bytes per tile
constexpr int BUFB = 2 * TILEB;          // A+B per stage

template <int MODE>
__global__ void __launch_bounds__(256, 2)
mma_gemm(const __nv_bfloat16* __restrict__ Ah, const __nv_bfloat16* __restrict__ Al,
         const __nv_bfloat16* __restrict__ Bh, const __nv_bfloat16* __restrict__ Bl,
         const float* __restrict__ bias, float* __restrict__ C,
         int M, int N, int K,
         const float* __restrict__ hidden, float* __restrict__ scOut) {
    __shared__ __align__(16) char smem[2 * BUFB];   // 40960 bytes
    const int t = threadIdx.x;
    const int lane = t & 31;
    const int wid = t >> 5;
    const int wm = wid & 1;      // 0..1  -> 64-row slab
    const int wn = wid >> 1;     // 0..3  -> 32-col slab
    const int m0 = blockIdx.y * GM, n0 = blockIdx.x * GN;
    const uint32_t sb = smem_u32(smem);

    float acc[4][4][4];
#pragma unroll
    for (int i = 0; i < 4; i++)
#pragma unroll
        for (int j = 0; j < 4; j++)
#pragma unroll
            for (int r = 0; r < 4; r++) acc[i][j][r] = 0.f;

    const __nv_bfloat16* Aps[3] = {Ah, Al, Ah};
    const __nv_bfloat16* Bps[3] = {Bh, Bh, Bl};
    const int KT = K / GK;
    const int T = 3 * KT;

    // per-thread load indices (2 chunks each for A and B)
    const int r0i = t >> 2, c0i = t & 3;          // chunk 0: rows 0..63
    const int r1i = r0i + 64;                      // chunk 1: rows 64..127

    auto issue_load = [&](int it, int buf) {
        const int pass = it / KT;
        const int kk = (it - pass * KT) * GK;
        const __nv_bfloat16* Ag = Aps[pass];
        const __nv_bfloat16* Bg = Bps[pass];
        uint32_t aB = sb + buf * BUFB;
        uint32_t bB = aB + TILEB;
        cp_async16(aB + r0i * ROWB + c0i * 16, Ag + (size_t)(m0 + r0i) * K + kk + c0i * 8);
        cp_async16(aB + r1i * ROWB + c0i * 16, Ag + (size_t)(m0 + r1i) * K + kk + c0i * 8);
        cp_async16(bB + r0i * ROWB + c0i * 16, Bg + (size_t)(n0 + r0i) * K + kk + c0i * 8);
        cp_async16(bB + r1i * ROWB + c0i * 16, Bg + (size_t)(n0 + r1i) * K + kk + c0i * 8);
        cp_commit();
    };

    // ldmatrix address components
    const int a_row = (lane & 15);                 // + wm*64 + mi*16
    const int a_kof = ((lane >> 4) & 1) * 16;
    const int b_row = ((lane >> 4) << 3) + (lane & 7);  // + wn*32 + njp*16
    const int b_kof = ((lane >> 3) & 1) * 16;

    issue_load(0, 0);
    for (int it = 0; it < T; ++it) {
        if (it + 1 < T) {
            issue_load(it + 1, (it + 1) & 1);
            cp_wait<1>();
        } else {
            cp_wait<0>();
        }
        __syncthreads();
        const uint32_t aB = sb + (it & 1) * BUFB;
        const uint32_t bB = aB + TILEB;
#pragma unroll
        for (int ks = 0; ks < 2; ks++) {
            uint32_t a[4][4], b[4][2];
#pragma unroll
            for (int mi = 0; mi < 4; mi++) {
                uint32_t addr = aB + (wm * 64 + mi * 16 + a_row) * ROWB + ks * 32 + a_kof;
                ldmx4(a[mi][0], a[mi][1], a[mi][2], a[mi][3], addr);
            }
#pragma unroll
            for (int njp = 0; njp < 2; njp++) {
                uint32_t addr = bB + (wn * 32 + njp * 16 + b_row) * ROWB + ks * 32 + b_kof;
                uint32_t q0, q1, q2, q3;
                ldmx4(q0, q1, q2, q3, addr);
                b[njp * 2][0] = q0; b[njp * 2][1] = q1;
                b[njp * 2 + 1][0] = q2; b[njp * 2 + 1][1] = q3;
            }
#pragma unroll
            for (int mi = 0; mi < 4; mi++)
#pragma unroll
                for (int nj = 0; nj < 4; nj++)
                    mma16816(acc[mi][nj], a[mi], b[nj]);
        }
        __syncthreads();
    }

    // ---------------- epilogue ----------------
    const int g = lane >> 2, q = lane & 3;
    if (MODE == 0) {
#pragma unroll
        for (int mi = 0; mi < 4; mi++) {
            int row0 = m0 + wm * 64 + mi * 16 + g;
            int row1 = row0 + 8;
#pragma unroll
            for (int nj = 0; nj < 4; nj++) {
                int col = n0 + wn * 32 + nj * 8 + 2 * q;
                float b0 = bias[col], b1 = bias[col + 1];
                float2 o0 = make_float2(acc[mi][nj][0] + b0, acc[mi][nj][1] + b1);
                float2 o1 = make_float2(acc[mi][nj][2] + b0, acc[mi][nj][3] + b1);
                *reinterpret_cast<float2*>(&C[(size_t)row0 * N + col]) = o0;
                *reinterpret_cast<float2*>(&C[(size_t)row1 * N + col]) = o1;
            }
        }
    } else {
        const int b = m0 >> 7;   // GM == S_ -> one batch row per M-tile
#pragma unroll
        for (int mi = 0; mi < 4; mi++) {
            float p0 = 0.f, p1 = 0.f;
#pragma unroll
            for (int nj = 0; nj < 4; nj++) {
                int col = n0 + wn * 32 + nj * 8 + 2 * q;
                float bz0 = bias[col], bz1 = bias[col + 1];
                float hv0 = hidden[b * H_ + col], hv1 = hidden[b * H_ + col + 1];
                p0 = fmaf(tanhf(acc[mi][nj][0] + bz0), hv0, p0);
                p0 = fmaf(tanhf(acc[mi][nj][1] + bz1), hv1, p0);
                p1 = fmaf(tanhf(acc[mi][nj][2] + bz0), hv0, p1);
                p1 = fmaf(tanhf(acc[mi][nj][3] + bz1), hv1, p1);
            }
            p0 += __shfl_xor_sync(0xffffffffu, p0, 1);
            p0 += __shfl_xor_sync(0xffffffffu, p0, 2);
            p1 += __shfl_xor_sync(0xffffffffu, p1, 1);
            p1 += __shfl_xor_sync(0xffffffffu, p1, 2);
            if (q == 0) {
                int row = m0 + wm * 64 + mi * 16 + g;
                atomicAdd(&scOut[row], p0);
                atomicAdd(&scOut[row + 8], p1);
            }
        }
    }
}

// ---------------- GRU + hidden split ----------------
__global__ void gru_kernel(const float* __restrict__ prev,
                           float* __restrict__ outHidden) {
    int idx = blockIdx.x * blockDim.x + threadIdx.x;
    int b = idx >> 9, h = idx & (H_ - 1);
    const float* gi = g_gi + (size_t)b * G_;
    const float* gh = g_gh + (size_t)b * G_;
    float ir = gi[h], iz = gi[h + H_], inn = gi[h + 2 * H_];
    float hr = gh[h], hz = gh[h + H_], hn = gh[h + 2 * H_];
    float r = 1.f / (1.f + expf(-(ir + hr)));
    float z = 1.f / (1.f + expf(-(iz + hz)));
    float n = tanhf(inn + r * hn);
    float hv = (1.f - z) * n + z * prev[idx];
    g_hidden[idx] = hv;
    outHidden[idx] = hv;
    __nv_bfloat16 hb = __float2bfloat16(hv);
    g_hid_hi[idx] = hb;
    g_hid_lo[idx] = __float2bfloat16(hv - __bfloat162float(hb));
}

// ---------------- softmax / scatter / attn ----------------
__global__ void __launch_bounds__(512)
softmax_kernel(float* __restrict__ pred, const int* __restrict__ src,
               const int* __restrict__ ids) {
    __shared__ float s_lc[S_];
    __shared__ float s_red[512];
    __shared__ int s_cnt;
    const int b = blockIdx.x, t = threadIdx.x;
    float* row = pred + (size_t)b * V_;

    if (t == 0) s_cnt = 0;
    if (t < S_) {
        float mask = (src[b * S_ + t] == 0) ? -1000.f : 0.f;
        s_lc[t] = tanhf(g_sc[b * S_ + t] + mask);
    }
    __syncthreads();

    float lmax = -1e30f;
    for (int v = t; v < V_; v += 512) lmax = fmaxf(lmax, row[v]);
    if (t < S_) lmax = fmaxf(lmax, s_lc[t]);
    s_red[t] = lmax;
    __syncthreads();
    for (int o = 256; o; o >>= 1) {
        if (t < o) s_red[t] = fmaxf(s_red[t], s_red[t + o]);
        __syncthreads();
    }
    float gmax = s_red[0];
    __syncthreads();

    float lsum = 0.f;
    for (int v = t; v < V_; v += 512) {
        float e = expf(row[v] - gmax);
        row[v] = e;
        lsum += e;
    }
    if (t < S_) lsum += expf(s_lc[t] - gmax);
    s_red[t] = lsum;
    __syncthreads();
    for (int o = 256; o; o >>= 1) {
        if (t < o) s_red[t] += s_red[t + o];
        __syncthreads();
    }
    float inv = 1.f / s_red[0];

    for (int v = t; v < V_; v += 512) row[v] *= inv;

    int id = ids[b];
    if (t < S_ && src[b * S_ + t] == id) atomicAdd(&s_cnt, 1);
    __syncthreads();

    if (t < S_) {
        float pc = expf(s_lc[t] - gmax) * inv;
        atomicAdd(&row[src[b * S_ + t]], pc);
        float eq = (src[b * S_ + t] == id) ? 1.f : 0.f;
        g_attn[b * S_ + t] = pc * eq / fmaxf((float)s_cnt, 1.f);
    }
}

__global__ void __launch_bounds__(256)
weighted_kernel(const float* __restrict__ enc, float* __restrict__ outW) {
    __shared__ float s_a[S_];
    const int b = blockIdx.x, t = threadIdx.x;
    if (t < S_) s_a[t] = g_attn[b * S_ + t];
    __syncthreads();
    float4 acc = make_float4(0.f, 0.f, 0.f, 0.f);
    const float4* e4 = reinterpret_cast<const float4*>(enc + (size_t)b * S_ * (2 * H_));
    for (int s = 0; s < S_; s++) {
        float w = s_a[s];
        if (w != 0.f) {
            float4 e = e4[s * 256 + t];
            acc.x = fmaf(w, e.x, acc.x); acc.y = fmaf(w, e.y, acc.y);
            acc.z = fmaf(w, e.z, acc.z); acc.w = fmaf(w, e.w, acc.w);
        }
    }
    reinterpret_cast<float4*>(outW)[b * 256 + t] = acc;
}

// ---------------- launch ----------------
extern "C" void kernel_launch(void* const* d_in, const int* in_sizes, int n_in,
                              void* d_out, int out_size) {
    const int*   input_ids = (const int*)d_in[0];
    const float* encoded   = (const float*)d_in[1];
    const int*   src       = (const int*)d_in[2];
    const float* prev      = (const float*)d_in[3];
    const float* weighted  = (const float*)d_in[4];
    const float* embed_w   = (const float*)d_in[6];
    const float* w_ih      = (const float*)d_in[7];
    const float* w_hh      = (const float*)d_in[8];
    const float* b_ih      = (const float*)d_in[9];
    const float* b_hh      = (const float*)d_in[10];
    const float* Wo_w      = (const float*)d_in[13];
    const float* Wo_b      = (const float*)d_in[14];
    const float* Wc_w      = (const float*)d_in[15];
    const float* Wc_b      = (const float*)d_in[16];

    float* pred        = (float*)d_out;
    float* outHidden   = pred + (size_t)B_ * V_;
    float* outWeighted = outHidden + (size_t)B_ * H_;

    float *px, *pgi, *pgh, *phid, *psc;
    cudaGetSymbolAddress((void**)&px,   g_x);
    cudaGetSymbolAddress((void**)&pgi,  g_gi);
    cudaGetSymbolAddress((void**)&pgh,  g_gh);
    cudaGetSymbolAddress((void**)&phid, g_hidden);
    cudaGetSymbolAddress((void**)&psc,  g_sc);
    __nv_bfloat16 *pench, *pencl, *pwoh, *pwol, *pwch, *pwcl, *phih, *phil;
    cudaGetSymbolAddress((void**)&pench, g_enc_hi);
    cudaGetSymbolAddress((void**)&pencl, g_enc_lo);
    cudaGetSymbolAddress((void**)&pwoh,  g_wo_hi);
    cudaGetSymbolAddress((void**)&pwol,  g_wo_lo);
    cudaGetSymbolAddress((void**)&pwch,  g_wc_hi);
    cudaGetSymbolAddress((void**)&pwcl,  g_wc_lo);
    cudaGetSymbolAddress((void**)&phih,  g_hid_hi);
    cudaGetSymbolAddress((void**)&phil,  g_hid_lo);

    // bf16 splits (independent of GRU chain)
    split_kernel<<<(B_ * S_ * 2 * H_) / 1024, 256>>>(encoded, pench, pencl, B_ * S_ * 2 * H_);
    split_kernel<<<(V_ * H_) / 1024, 256>>>(Wo_w, pwoh, pwol, V_ * H_);
    split_kernel<<<(H_ * 2 * H_) / 1024, 256>>>(Wc_w, pwch, pwcl, H_ * 2 * H_);

    // GRU chain (fp32)
    build_x_kernel<<<(B_ * IN_) / 256, 256>>>(input_ids, embed_w, weighted);
    sgemm_kernel<<<dim3(G_ / BNr, B_ / BMr), 256>>>(px, w_ih, b_ih, pgi, B_, G_, IN_);
    sgemm_kernel<<<dim3(G_ / BNr, B_ / BMr), 256>>>(prev, w_hh, b_hh, pgh, B_, G_, H_);
    gru_kernel<<<(B_ * H_) / 256, 256>>>(prev, outHidden);

    // score_g = hidden @ Wo^T + Wo_b   (HMMA, 3-pass bf16 split)
    mma_gemm<0><<<dim3(V_ / GN, B_ / GM), 256>>>(
        phih, phil, pwoh, pwol, Wo_b, pred, B_, V_, H_, nullptr, nullptr);

    // sc = einsum(tanh(enc @ Wc^T + Wc_b), hidden)  (fused epilogue)
    zero_sc_kernel<<<(B_ * S_) / 256, 256>>>();
    mma_gemm<1><<<dim3(H_ / GN, (B_ * S_) / GM), 256>>>(
        pench, pencl, pwch, pwcl, Wc_b, nullptr, B_ * S_, H_, 2 * H_, phid, psc);

    softmax_kernel<<<B_, 512>>>(pred, src, input_ids);
    weighted_kernel<<<B_, 256>>>(encoded, outWeighted);

    (void)in_sizes; (void)n_in; (void)out_size;
}

// round 4
// speedup vs baseline: 2.0779x; 1.0978x over previous
#include <cuda_runtime.h>
#include <cuda_bf16.h>
#include <math.h>
#include <stdint.h>

namespace {
constexpr int B_ = 256;
constexpr int S_ = 128;
constexpr int H_ = 512;
constexpr int E_ = 512;
constexpr int V_ = 32000;
constexpr int IN_ = E_ + 2 * H_;   // 1536
constexpr int G_ = 3 * H_;         // 1536
}

// ---------------- static scratch ----------------
__device__ float g_gi[B_ * G_];
__device__ float g_gh[B_ * G_];
__device__ float g_hidden[B_ * H_];
__device__ float g_sc[B_ * S_];
__device__ float g_attn[B_ * S_];

__device__ __nv_bfloat16 g_enc_hi[B_ * S_ * 2 * H_];
__device__ __nv_bfloat16 g_enc_lo[B_ * S_ * 2 * H_];
__device__ __nv_bfloat16 g_wo_hi[V_ * H_];
__device__ __nv_bfloat16 g_wo_lo[V_ * H_];
__device__ __nv_bfloat16 g_wc_hi[H_ * 2 * H_];
__device__ __nv_bfloat16 g_wc_lo[H_ * 2 * H_];
__device__ __nv_bfloat16 g_hid_hi[B_ * H_];
__device__ __nv_bfloat16 g_hid_lo[B_ * H_];
__device__ __nv_bfloat16 g_x_hi[B_ * IN_];
__device__ __nv_bfloat16 g_x_lo[B_ * IN_];
__device__ __nv_bfloat16 g_prev_hi[B_ * H_];
__device__ __nv_bfloat16 g_prev_lo[B_ * H_];
__device__ __nv_bfloat16 g_wih_hi[G_ * IN_];
__device__ __nv_bfloat16 g_wih_lo[G_ * IN_];
__device__ __nv_bfloat16 g_whh_hi[G_ * H_];
__device__ __nv_bfloat16 g_whh_lo[G_ * H_];

// ---------------- helpers ----------------
__device__ __forceinline__ uint32_t smem_u32(const void* p) {
    uint32_t a;
    asm("{ .reg .u64 t; cvta.to.shared.u64 t, %1; cvt.u32.u64 %0, t; }"
        : "=r"(a) : "l"(p));
    return a;
}
__device__ __forceinline__ void cp_async16(uint32_t s, const void* g) {
    asm volatile("cp.async.cg.shared.global [%0], [%1], 16;\n"
                 :: "r"(s), "l"(g) : "memory");
}
__device__ __forceinline__ void cp_commit() {
    asm volatile("cp.async.commit_group;\n" ::: "memory");
}
template <int N>
__device__ __forceinline__ void cp_wait() {
    asm volatile("cp.async.wait_group %0;\n" :: "n"(N) : "memory");
}
__device__ __forceinline__ void ldmx4(uint32_t& r0, uint32_t& r1, uint32_t& r2,
                                      uint32_t& r3, uint32_t addr) {
    asm volatile("ldmatrix.sync.aligned.m8n8.x4.shared.b16 {%0,%1,%2,%3}, [%4];\n"
                 : "=r"(r0), "=r"(r1), "=r"(r2), "=r"(r3) : "r"(addr));
}
__device__ __forceinline__ void mma16816(float* d, const uint32_t* a,
                                         const uint32_t* b) {
    asm volatile(
        "mma.sync.aligned.m16n8k16.row.col.f32.bf16.bf16.f32 "
        "{%0,%1,%2,%3}, {%4,%5,%6,%7}, {%8,%9}, {%0,%1,%2,%3};\n"
        : "+f"(d[0]), "+f"(d[1]), "+f"(d[2]), "+f"(d[3])
        : "r"(a[0]), "r"(a[1]), "r"(a[2]), "r"(a[3]), "r"(b[0]), "r"(b[1]));
}

// ---------------- elementwise kernels ----------------
// x = concat(embed[ids], weighted) split straight to bf16 hi/lo
__global__ void build_x_split_kernel(const int* __restrict__ ids,
                                     const float* __restrict__ emb,
                                     const float* __restrict__ weighted) {
    int idx = blockIdx.x * blockDim.x + threadIdx.x;  // < B*IN
    int b = idx / IN_;
    int j = idx - b * IN_;
    float v = (j < E_) ? emb[(size_t)ids[b] * E_ + j]
                       : weighted[b * (2 * H_) + (j - E_)];
    __nv_bfloat16 h = __float2bfloat16(v);
    g_x_hi[idx] = h;
    g_x_lo[idx] = __float2bfloat16(v - __bfloat162float(h));
}

__global__ void zero_sc_kernel() {
    int idx = blockIdx.x * blockDim.x + threadIdx.x;
    g_sc[idx] = 0.f;
}

__global__ void split_kernel(const float* __restrict__ s,
                             __nv_bfloat16* __restrict__ hi,
                             __nv_bfloat16* __restrict__ lo, int n) {
    int i = (blockIdx.x * blockDim.x + threadIdx.x) * 4;
    if (i >= n) return;
    float4 v = *reinterpret_cast<const float4*>(s + i);
    __nv_bfloat16 h0 = __float2bfloat16(v.x);
    __nv_bfloat16 h1 = __float2bfloat16(v.y);
    __nv_bfloat16 h2 = __float2bfloat16(v.z);
    __nv_bfloat16 h3 = __float2bfloat16(v.w);
    __nv_bfloat16 l0 = __float2bfloat16(v.x - __bfloat162float(h0));
    __nv_bfloat16 l1 = __float2bfloat16(v.y - __bfloat162float(h1));
    __nv_bfloat16 l2 = __float2bfloat16(v.z - __bfloat162float(h2));
    __nv_bfloat16 l3 = __float2bfloat16(v.w - __bfloat162float(h3));
    reinterpret_cast<__nv_bfloat162*>(hi + i)[0] = __nv_bfloat162(h0, h1);
    reinterpret_cast<__nv_bfloat162*>(hi + i)[1] = __nv_bfloat162(h2, h3);
    reinterpret_cast<__nv_bfloat162*>(lo + i)[0] = __nv_bfloat162(l0, l1);
    reinterpret_cast<__nv_bfloat162*>(lo + i)[1] = __nv_bfloat162(l2, l3);
}

// ---------------- mma.sync bf16 split GEMM (3-stage cp.async) ----------------
// C[M,N] = A[M,K] @ W[N,K]^T via 3-pass bf16 split (hi*hi + lo*hi + hi*lo)
// MODE 0: C[m,n] = acc + bias[n]
// MODE 1: sc[m] += sum_n tanh(acc + bias[n]) * hidden[m>>7, n]
constexpr int GM = 128, GN = 128;
constexpr int ROWB = 80;                 // padded row stride (bytes) for 64B rows
constexpr int TILEB = 128 * ROWB;        // 10240 bytes per tile
constexpr int BUFB = 2 * TILEB;          // A+B per stage
constexpr int STAGES = 3;
constexpr int MMA_SMEM = STAGES * BUFB;  // 61440 bytes

template <int MODE>
__global__ void __launch_bounds__(256, 2)
mma_gemm(const __nv_bfloat16* __restrict__ Ah, const __nv_bfloat16* __restrict__ Al,
         const __nv_bfloat16* __restrict__ Bh, const __nv_bfloat16* __restrict__ Bl,
         const float* __restrict__ bias, float* __restrict__ C,
         int M, int N, int K,
         const float* __restrict__ hidden, float* __restrict__ scOut) {
    extern __shared__ __align__(16) char smem[];
    const int t = threadIdx.x;
    const int lane = t & 31;
    const int wid = t >> 5;
    const int wm = wid & 1;      // 64-row slab
    const int wn = wid >> 1;     // 32-col slab
    const int m0 = blockIdx.y * GM, n0 = blockIdx.x * GN;
    const uint32_t sb = smem_u32(smem);

    float acc[4][4][4];
#pragma unroll
    for (int i = 0; i < 4; i++)
#pragma unroll
        for (int j = 0; j < 4; j++)
#pragma unroll
            for (int r = 0; r < 4; r++) acc[i][j][r] = 0.f;

    const __nv_bfloat16* Aps[3] = {Ah, Al, Ah};
    const __nv_bfloat16* Bps[3] = {Bh, Bh, Bl};
    const int KT = K / 32;
    const int T = 3 * KT;

    const int r0i = t >> 2, c0i = t & 3;
    const int r1i = r0i + 64;

    auto issue_load = [&](int it) {
        const int pass = it / KT;
        const int kk = (it - pass * KT) * 32;
        const __nv_bfloat16* Ag = Aps[pass];
        const __nv_bfloat16* Bg = Bps[pass];
        uint32_t aB = sb + (it % STAGES) * BUFB;
        uint32_t bB = aB + TILEB;
        cp_async16(aB + r0i * ROWB + c0i * 16, Ag + (size_t)(m0 + r0i) * K + kk + c0i * 8);
        cp_async16(aB + r1i * ROWB + c0i * 16, Ag + (size_t)(m0 + r1i) * K + kk + c0i * 8);
        cp_async16(bB + r0i * ROWB + c0i * 16, Bg + (size_t)(n0 + r0i) * K + kk + c0i * 8);
        cp_async16(bB + r1i * ROWB + c0i * 16, Bg + (size_t)(n0 + r1i) * K + kk + c0i * 8);
        cp_commit();
    };

    const int a_row = (lane & 15);
    const int a_kof = ((lane >> 4) & 1) * 16;
    const int b_row = ((lane >> 4) << 3) + (lane & 7);
    const int b_kof = ((lane >> 3) & 1) * 16;

    issue_load(0);
    issue_load(1);
    for (int it = 0; it < T; ++it) {
        if (it + 1 < T) cp_wait<1>(); else cp_wait<0>();
        __syncthreads();
        if (it + 2 < T) issue_load(it + 2);
        const uint32_t aB = sb + (it % STAGES) * BUFB;
        const uint32_t bB = aB + TILEB;
#pragma unroll
        for (int ks = 0; ks < 2; ks++) {
            uint32_t a[4][4], b[4][2];
#pragma unroll
            for (int mi = 0; mi < 4; mi++) {
                uint32_t addr = aB + (wm * 64 + mi * 16 + a_row) * ROWB + ks * 32 + a_kof;
                ldmx4(a[mi][0], a[mi][1], a[mi][2], a[mi][3], addr);
            }
#pragma unroll
            for (int njp = 0; njp < 2; njp++) {
                uint32_t addr = bB + (wn * 32 + njp * 16 + b_row) * ROWB + ks * 32 + b_kof;
                uint32_t q0, q1, q2, q3;
                ldmx4(q0, q1, q2, q3, addr);
                b[njp * 2][0] = q0; b[njp * 2][1] = q1;
                b[njp * 2 + 1][0] = q2; b[njp * 2 + 1][1] = q3;
            }
#pragma unroll
            for (int mi = 0; mi < 4; mi++)
#pragma unroll
                for (int nj = 0; nj < 4; nj++)
                    mma16816(acc[mi][nj], a[mi], b[nj]);
        }
    }

    // ---------------- epilogue ----------------
    const int g = lane >> 2, q = lane & 3;
    if (MODE == 0) {
#pragma unroll
        for (int mi = 0; mi < 4; mi++) {
            int row0 = m0 + wm * 64 + mi * 16 + g;
            int row1 = row0 + 8;
#pragma unroll
            for (int nj = 0; nj < 4; nj++) {
                int col = n0 + wn * 32 + nj * 8 + 2 * q;
                float b0 = bias[col], b1 = bias[col + 1];
                float2 o0 = make_float2(acc[mi][nj][0] + b0, acc[mi][nj][1] + b1);
                float2 o1 = make_float2(acc[mi][nj][2] + b0, acc[mi][nj][3] + b1);
                *reinterpret_cast<float2*>(&C[(size_t)row0 * N + col]) = o0;
                *reinterpret_cast<float2*>(&C[(size_t)row1 * N + col]) = o1;
            }
        }
    } else {
        const int b = m0 >> 7;   // GM == S_
#pragma unroll
        for (int mi = 0; mi < 4; mi++) {
            float p0 = 0.f, p1 = 0.f;
#pragma unroll
            for (int nj = 0; nj < 4; nj++) {
                int col = n0 + wn * 32 + nj * 8 + 2 * q;
                float bz0 = bias[col], bz1 = bias[col + 1];
                float hv0 = hidden[b * H_ + col], hv1 = hidden[b * H_ + col + 1];
                p0 = fmaf(tanhf(acc[mi][nj][0] + bz0), hv0, p0);
                p0 = fmaf(tanhf(acc[mi][nj][1] + bz1), hv1, p0);
                p1 = fmaf(tanhf(acc[mi][nj][2] + bz0), hv0, p1);
                p1 = fmaf(tanhf(acc[mi][nj][3] + bz1), hv1, p1);
            }
            p0 += __shfl_xor_sync(0xffffffffu, p0, 1);
            p0 += __shfl_xor_sync(0xffffffffu, p0, 2);
            p1 += __shfl_xor_sync(0xffffffffu, p1, 1);
            p1 += __shfl_xor_sync(0xffffffffu, p1, 2);
            if (q == 0) {
                int row = m0 + wm * 64 + mi * 16 + g;
                atomicAdd(&scOut[row], p0);
                atomicAdd(&scOut[row + 8], p1);
            }
        }
    }
}

// ---------------- GRU + hidden split ----------------
__global__ void gru_kernel(const float* __restrict__ prev,
                           float* __restrict__ outHidden) {
    int idx = blockIdx.x * blockDim.x + threadIdx.x;
    int b = idx >> 9, h = idx & (H_ - 1);
    const float* gi = g_gi + (size_t)b * G_;
    const float* gh = g_gh + (size_t)b * G_;
    float ir = gi[h], iz = gi[h + H_], inn = gi[h + 2 * H_];
    float hr = gh[h], hz = gh[h + H_], hn = gh[h + 2 * H_];
    float r = 1.f / (1.f + expf(-(ir + hr)));
    float z = 1.f / (1.f + expf(-(iz + hz)));
    float n = tanhf(inn + r * hn);
    float hv = (1.f - z) * n + z * prev[idx];
    g_hidden[idx] = hv;
    outHidden[idx] = hv;
    __nv_bfloat16 hb = __float2bfloat16(hv);
    g_hid_hi[idx] = hb;
    g_hid_lo[idx] = __float2bfloat16(hv - __bfloat162float(hb));
}

// ---------------- softmax (online max+sum, 2 global passes) ----------------
__global__ void __launch_bounds__(512)
softmax_kernel(float* __restrict__ pred, const int* __restrict__ src,
               const int* __restrict__ ids) {
    __shared__ float s_lc[S_];
    __shared__ float s_m[512];
    __shared__ float s_s[512];
    __shared__ int s_cnt;
    const int b = blockIdx.x, t = threadIdx.x;
    float* row = pred + (size_t)b * V_;

    if (t == 0) s_cnt = 0;
    if (t < S_) {
        float mask = (src[b * S_ + t] == 0) ? -1000.f : 0.f;
        s_lc[t] = tanhf(g_sc[b * S_ + t] + mask);
    }
    __syncthreads();

    // online (max, sum)
    float m = -1e30f, s = 0.f;
    for (int v = t; v < V_; v += 512) {
        float x = row[v];
        float nm = fmaxf(m, x);
        s = s * expf(m - nm) + expf(x - nm);
        m = nm;
    }
    if (t < S_) {
        float x = s_lc[t];
        float nm = fmaxf(m, x);
        s = s * expf(m - nm) + expf(x - nm);
        m = nm;
    }
    s_m[t] = m; s_s[t] = s;
    __syncthreads();
    for (int o = 256; o; o >>= 1) {
        if (t < o) {
            float m1 = s_m[t], m2 = s_m[t + o];
            float nm = fmaxf(m1, m2);
            s_s[t] = s_s[t] * expf(m1 - nm) + s_s[t + o] * expf(m2 - nm);
            s_m[t] = nm;
        }
        __syncthreads();
    }
    float gmax = s_m[0];
    float inv = 1.f / s_s[0];

    for (int v = t; v < V_; v += 512) row[v] = expf(row[v] - gmax) * inv;

    int id = ids[b];
    if (t < S_ && src[b * S_ + t] == id) atomicAdd(&s_cnt, 1);
    __syncthreads();

    if (t < S_) {
        float pc = expf(s_lc[t] - gmax) * inv;
        atomicAdd(&row[src[b * S_ + t]], pc);
        float eq = (src[b * S_ + t] == id) ? 1.f : 0.f;
        g_attn[b * S_ + t] = pc * eq / fmaxf((float)s_cnt, 1.f);
    }
}

__global__ void __launch_bounds__(256)
weighted_kernel(const float* __restrict__ enc, float* __restrict__ outW) {
    __shared__ float s_a[S_];
    const int b = blockIdx.x, t = threadIdx.x;
    if (t < S_) s_a[t] = g_attn[b * S_ + t];
    __syncthreads();
    float4 acc = make_float4(0.f, 0.f, 0.f, 0.f);
    const float4* e4 = reinterpret_cast<const float4*>(enc + (size_t)b * S_ * (2 * H_));
    for (int s = 0; s < S_; s++) {
        float w = s_a[s];
        if (w != 0.f) {
            float4 e = e4[s * 256 + t];
            acc.x = fmaf(w, e.x, acc.x); acc.y = fmaf(w, e.y, acc.y);
            acc.z = fmaf(w, e.z, acc.z); acc.w = fmaf(w, e.w, acc.w);
        }
    }
    reinterpret_cast<float4*>(outW)[b * 256 + t] = acc;
}

// ---------------- launch ----------------
extern "C" void kernel_launch(void* const* d_in, const int* in_sizes, int n_in,
                              void* d_out, int out_size) {
    const int*   input_ids = (const int*)d_in[0];
    const float* encoded   = (const float*)d_in[1];
    const int*   src       = (const int*)d_in[2];
    const float* prev      = (const float*)d_in[3];
    const float* weighted  = (const float*)d_in[4];
    const float* embed_w   = (const float*)d_in[6];
    const float* w_ih      = (const float*)d_in[7];
    const float* w_hh      = (const float*)d_in[8];
    const float* b_ih      = (const float*)d_in[9];
    const float* b_hh      = (const float*)d_in[10];
    const float* Wo_w      = (const float*)d_in[13];
    const float* Wo_b      = (const float*)d_in[14];
    const float* Wc_w      = (const float*)d_in[15];
    const float* Wc_b      = (const float*)d_in[16];

    float* pred        = (float*)d_out;
    float* outHidden   = pred + (size_t)B_ * V_;
    float* outWeighted = outHidden + (size_t)B_ * H_;

    float *pgi, *pgh, *phid, *psc;
    cudaGetSymbolAddress((void**)&pgi,  g_gi);
    cudaGetSymbolAddress((void**)&pgh,  g_gh);
    cudaGetSymbolAddress((void**)&phid, g_hidden);
    cudaGetSymbolAddress((void**)&psc,  g_sc);
    __nv_bfloat16 *pench, *pencl, *pwoh, *pwol, *pwch, *pwcl, *phih, *phil;
    __nv_bfloat16 *pxh, *pxl, *pph, *ppl, *pwihh, *pwihl, *pwhhh, *pwhhl;
    cudaGetSymbolAddress((void**)&pench, g_enc_hi);
    cudaGetSymbolAddress((void**)&pencl, g_enc_lo);
    cudaGetSymbolAddress((void**)&pwoh,  g_wo_hi);
    cudaGetSymbolAddress((void**)&pwol,  g_wo_lo);
    cudaGetSymbolAddress((void**)&pwch,  g_wc_hi);
    cudaGetSymbolAddress((void**)&pwcl,  g_wc_lo);
    cudaGetSymbolAddress((void**)&phih,  g_hid_hi);
    cudaGetSymbolAddress((void**)&phil,  g_hid_lo);
    cudaGetSymbolAddress((void**)&pxh,   g_x_hi);
    cudaGetSymbolAddress((void**)&pxl,   g_x_lo);
    cudaGetSymbolAddress((void**)&pph,   g_prev_hi);
    cudaGetSymbolAddress((void**)&ppl,   g_prev_lo);
    cudaGetSymbolAddress((void**)&pwihh, g_wih_hi);
    cudaGetSymbolAddress((void**)&pwihl, g_wih_lo);
    cudaGetSymbolAddress((void**)&pwhhh, g_whh_hi);
    cudaGetSymbolAddress((void**)&pwhhl, g_whh_lo);

    cudaFuncSetAttribute(mma_gemm<0>, cudaFuncAttributeMaxDynamicSharedMemorySize, MMA_SMEM);
    cudaFuncSetAttribute(mma_gemm<1>, cudaFuncAttributeMaxDynamicSharedMemorySize, MMA_SMEM);

    // splits
    build_x_split_kernel<<<(B_ * IN_) / 256, 256>>>(input_ids, embed_w, weighted);
    split_kernel<<<(B_ * H_) / 1024, 256>>>(prev, pph, ppl, B_ * H_);
    split_kernel<<<(G_ * IN_) / 1024, 256>>>(w_ih, pwihh, pwihl, G_ * IN_);
    split_kernel<<<(G_ * H_) / 1024, 256>>>(w_hh, pwhhh, pwhhl, G_ * H_);
    split_kernel<<<(B_ * S_ * 2 * H_) / 1024, 256>>>(encoded, pench, pencl, B_ * S_ * 2 * H_);
    split_kernel<<<(V_ * H_) / 1024, 256>>>(Wo_w, pwoh, pwol, V_ * H_);
    split_kernel<<<(H_ * 2 * H_) / 1024, 256>>>(Wc_w, pwch, pwcl, H_ * 2 * H_);

    // gi = x @ W_ih^T + b_ih;  gh = prev @ W_hh^T + b_hh  (HMMA)
    mma_gemm<0><<<dim3(G_ / GN, B_ / GM), 256, MMA_SMEM>>>(
        pxh, pxl, pwihh, pwihl, b_ih, pgi, B_, G_, IN_, nullptr, nullptr);
    mma_gemm<0><<<dim3(G_ / GN, B_ / GM), 256, MMA_SMEM>>>(
        pph, ppl, pwhhh, pwhhl, b_hh, pgh, B_, G_, H_, nullptr, nullptr);

    gru_kernel<<<(B_ * H_) / 256, 256>>>(prev, outHidden);

    // score_g = hidden @ Wo^T + Wo_b
    mma_gemm<0><<<dim3(V_ / GN, B_ / GM), 256, MMA_SMEM>>>(
        phih, phil, pwoh, pwol, Wo_b, pred, B_, V_, H_, nullptr, nullptr);

    // sc = einsum(tanh(enc @ Wc^T + Wc_b), hidden)
    zero_sc_kernel<<<(B_ * S_) / 256, 256>>>();
    mma_gemm<1><<<dim3(H_ / GN, (B_ * S_) / GM), 256, MMA_SMEM>>>(
        pench, pencl, pwch, pwcl, Wc_b, nullptr, B_ * S_, H_, 2 * H_, phid, psc);

    softmax_kernel<<<B_, 512>>>(pred, src, input_ids);
    weighted_kernel<<<B_, 256>>>(encoded, outWeighted);

    (void)in_sizes; (void)n_in; (void)out_size;
}

// round 5
// speedup vs baseline: 2.2570x; 1.0862x over previous
#include <cuda_runtime.h>
#include <cuda_bf16.h>
#include <math.h>
#include <stdint.h>

namespace {
constexpr int B_ = 256;
constexpr int S_ = 128;
constexpr int H_ = 512;
constexpr int E_ = 512;
constexpr int V_ = 32000;
constexpr int IN_ = E_ + 2 * H_;   // 1536
constexpr int G_ = 3 * H_;         // 1536
}

// ---------------- static scratch ----------------
__device__ float g_x[B_ * IN_];
__device__ float g_gi[B_ * G_];
__device__ float g_gh[B_ * G_];
__device__ float g_hidden[B_ * H_];
__device__ float g_sc[B_ * S_];
__device__ float g_attn[B_ * S_];

// ---------------- helpers ----------------
__device__ __forceinline__ uint32_t smem_u32(const void* p) {
    uint32_t a;
    asm("{ .reg .u64 t; cvta.to.shared.u64 t, %1; cvt.u32.u64 %0, t; }"
        : "=r"(a) : "l"(p));
    return a;
}
__device__ __forceinline__ void cp_async16(uint32_t s, const void* g) {
    asm volatile("cp.async.cg.shared.global [%0], [%1], 16;\n"
                 :: "r"(s), "l"(g) : "memory");
}
__device__ __forceinline__ void cp_commit() {
    asm volatile("cp.async.commit_group;\n" ::: "memory");
}
template <int N>
__device__ __forceinline__ void cp_wait() {
    asm volatile("cp.async.wait_group %0;\n" :: "n"(N) : "memory");
}
__device__ __forceinline__ void ldmx4(uint32_t& r0, uint32_t& r1, uint32_t& r2,
                                      uint32_t& r3, uint32_t addr) {
    asm volatile("ldmatrix.sync.aligned.m8n8.x4.shared.b16 {%0,%1,%2,%3}, [%4];\n"
                 : "=r"(r0), "=r"(r1), "=r"(r2), "=r"(r3) : "r"(addr));
}
__device__ __forceinline__ void mma16816(float* d, const uint32_t* a,
                                         const uint32_t* b) {
    asm volatile(
        "mma.sync.aligned.m16n8k16.row.col.f32.bf16.bf16.f32 "
        "{%0,%1,%2,%3}, {%4,%5,%6,%7}, {%8,%9}, {%0,%1,%2,%3};\n"
        : "+f"(d[0]), "+f"(d[1]), "+f"(d[2]), "+f"(d[3])
        : "r"(a[0]), "r"(a[1]), "r"(a[2]), "r"(a[3]), "r"(b[0]), "r"(b[1]));
}
__device__ __forceinline__ uint32_t bfbits(__nv_bfloat16 h) {
    return (uint32_t)__nv_bfloat16_raw(h).x;
}
// float4 -> packed hi (2x u32) and lo (2x u32)
__device__ __forceinline__ void cvt4(float4 v, uint32_t& h0, uint32_t& h1,
                                     uint32_t& l0, uint32_t& l1) {
    __nv_bfloat16 hx = __float2bfloat16(v.x);
    __nv_bfloat16 hy = __float2bfloat16(v.y);
    __nv_bfloat16 hz = __float2bfloat16(v.z);
    __nv_bfloat16 hw = __float2bfloat16(v.w);
    __nv_bfloat16 lx = __float2bfloat16(v.x - __bfloat162float(hx));
    __nv_bfloat16 ly = __float2bfloat16(v.y - __bfloat162float(hy));
    __nv_bfloat16 lz = __float2bfloat16(v.z - __bfloat162float(hz));
    __nv_bfloat16 lw = __float2bfloat16(v.w - __bfloat162float(hw));
    h0 = bfbits(hx) | (bfbits(hy) << 16);
    h1 = bfbits(hz) | (bfbits(hw) << 16);
    l0 = bfbits(lx) | (bfbits(ly) << 16);
    l1 = bfbits(lz) | (bfbits(lw) << 16);
}

// ---------------- elementwise kernels ----------------
__global__ void build_x_kernel(const int* __restrict__ ids,
                               const float* __restrict__ emb,
                               const float* __restrict__ weighted) {
    int idx = blockIdx.x * blockDim.x + threadIdx.x;  // < B*IN
    int b = idx / IN_;
    int j = idx - b * IN_;
    g_x[idx] = (j < E_) ? emb[(size_t)ids[b] * E_ + j]
                        : weighted[b * (2 * H_) + (j - E_)];
}

__global__ void zero_sc_kernel() {
    int idx = blockIdx.x * blockDim.x + threadIdx.x;
    g_sc[idx] = 0.f;
}

// ---------------- fused split + mma.sync GEMM ----------------
// C[M,N] = A[M,K] @ W[N,K]^T in fp32-equivalent precision.
// fp32 tiles staged via cp.async, converted in-kernel to bf16 hi/lo,
// 3 split passes (hi*hi + lo*hi + hi*lo) per 32-wide K chunk.
// MODE 0: C[m,n] = acc + bias[n]
// MODE 1: sc[m] += sum_n tanh(acc + bias[n]) * hidden[m>>7, n]
constexpr int GM = 128, GN = 128;
constexpr int ROWB = 80;                   // bf16 tile row stride (64B data + pad)
constexpr int BTILE = 128 * ROWB;          // 10240 B per bf16 tile
constexpr int STG = 128 * 128;             // 16384 B per fp32 staging tile
constexpr int STG_STAGE = 2 * STG;         // A + B per stage
constexpr uint32_t BF_BASE = 2 * STG_STAGE;    // 65536
constexpr uint32_t AH_O = BF_BASE;
constexpr uint32_t AL_O = BF_BASE + BTILE;
constexpr uint32_t BH_O = BF_BASE + 2 * BTILE;
constexpr uint32_t BL_O = BF_BASE + 3 * BTILE;
constexpr int MMA_SMEM = BF_BASE + 4 * BTILE;  // 106496 B

__device__ __forceinline__ uint32_t stg_sw(int row, int byteInRow) {
    uint32_t off = (uint32_t)(row * 128 + byteInRow);
    return off ^ ((uint32_t)(row & 7) << 4);
}

template <int MODE>
__global__ void __launch_bounds__(256, 2)
mma_gemm(const float* __restrict__ Af, const float* __restrict__ Bf,
         const float* __restrict__ bias, float* __restrict__ C,
         int M, int N, int K,
         const float* __restrict__ hidden, float* __restrict__ scOut) {
    extern __shared__ __align__(16) char smem[];
    const int t = threadIdx.x;
    const int lane = t & 31;
    const int wid = t >> 5;
    const int wm = wid & 1;      // 64-row slab
    const int wn = wid >> 1;     // 32-col slab
    const int m0 = blockIdx.y * GM, n0 = blockIdx.x * GN;
    const uint32_t sb = smem_u32(smem);

    float acc[4][4][4];
#pragma unroll
    for (int i = 0; i < 4; i++)
#pragma unroll
        for (int j = 0; j < 4; j++)
#pragma unroll
            for (int r = 0; r < 4; r++) acc[i][j][r] = 0.f;

    const int KT = K / 32;
    const int cr = t >> 2;              // load/convert row 0..63 (+64)
    const int cq = t & 3;               // 32B column quad

    auto issue_load = [&](int it) {
        const int kk = it * 32;
        uint32_t stA = sb + (it & 1) * STG_STAGE;
        uint32_t stB = stA + STG;
        const float* Ap = Af + (size_t)(m0 + cr) * K + kk + cq * 8;
        const float* Bp = Bf + (size_t)(n0 + cr) * K + kk + cq * 8;
#pragma unroll
        for (int h = 0; h < 2; h++) {   // rows cr, cr+64
            int row = cr + h * 64;
            cp_async16(stA + stg_sw(row, cq * 32),      Ap + (size_t)h * 64 * K);
            cp_async16(stA + stg_sw(row, cq * 32 + 16), Ap + (size_t)h * 64 * K + 4);
            cp_async16(stB + stg_sw(row, cq * 32),      Bp + (size_t)h * 64 * K);
            cp_async16(stB + stg_sw(row, cq * 32 + 16), Bp + (size_t)h * 64 * K + 4);
        }
        cp_commit();
    };

    const int a_row = (lane & 15);
    const int a_kof = ((lane >> 4) & 1) * 16;
    const int b_row = ((lane >> 4) << 3) + (lane & 7);
    const int b_kof = ((lane >> 3) & 1) * 16;

    issue_load(0);
    if (KT > 1) issue_load(1);

    for (int it = 0; it < KT; ++it) {
        if (it + 1 < KT) cp_wait<1>(); else cp_wait<0>();
        __syncthreads();   // staging ready; prior-iter ldmatrix complete everywhere

        // convert fp32 staging -> bf16 hi/lo tiles
        {
            uint32_t stA = sb + (it & 1) * STG_STAGE;
            uint32_t stB = stA + STG;
#pragma unroll
            for (int h = 0; h < 2; h++) {
                int row = cr + h * 64;
                uint32_t so0 = stg_sw(row, cq * 32);
                uint32_t so1 = stg_sw(row, cq * 32 + 16);
                uint32_t dof = (uint32_t)(row * ROWB + cq * 16);
                // A
                float4 va0 = *reinterpret_cast<const float4*>(smem + (stA - sb) + so0);
                float4 va1 = *reinterpret_cast<const float4*>(smem + (stA - sb) + so1);
                uint32_t h0, h1, h2, h3, l0, l1, l2, l3;
                cvt4(va0, h0, h1, l0, l1);
                cvt4(va1, h2, h3, l2, l3);
                *reinterpret_cast<uint4*>(smem + AH_O + dof) = make_uint4(h0, h1, h2, h3);
                *reinterpret_cast<uint4*>(smem + AL_O + dof) = make_uint4(l0, l1, l2, l3);
                // B
                float4 vb0 = *reinterpret_cast<const float4*>(smem + (stB - sb) + so0);
                float4 vb1 = *reinterpret_cast<const float4*>(smem + (stB - sb) + so1);
                cvt4(vb0, h0, h1, l0, l1);
                cvt4(vb1, h2, h3, l2, l3);
                *reinterpret_cast<uint4*>(smem + BH_O + dof) = make_uint4(h0, h1, h2, h3);
                *reinterpret_cast<uint4*>(smem + BL_O + dof) = make_uint4(l0, l1, l2, l3);
            }
        }
        __syncthreads();   // bf16 tiles visible; staging free for reuse

        if (it + 2 < KT) issue_load(it + 2);

        // 3 split passes over this chunk
#pragma unroll
        for (int p = 0; p < 3; p++) {
            const uint32_t aT = sb + ((p == 1) ? AL_O : AH_O);
            const uint32_t bT = sb + ((p == 2) ? BL_O : BH_O);
#pragma unroll
            for (int ks = 0; ks < 2; ks++) {
                uint32_t a[4][4], b[4][2];
#pragma unroll
                for (int mi = 0; mi < 4; mi++) {
                    uint32_t addr = aT + (wm * 64 + mi * 16 + a_row) * ROWB + ks * 32 + a_kof;
                    ldmx4(a[mi][0], a[mi][1], a[mi][2], a[mi][3], addr);
                }
#pragma unroll
                for (int njp = 0; njp < 2; njp++) {
                    uint32_t addr = bT + (wn * 32 + njp * 16 + b_row) * ROWB + ks * 32 + b_kof;
                    uint32_t q0, q1, q2, q3;
                    ldmx4(q0, q1, q2, q3, addr);
                    b[njp * 2][0] = q0; b[njp * 2][1] = q1;
                    b[njp * 2 + 1][0] = q2; b[njp * 2 + 1][1] = q3;
                }
#pragma unroll
                for (int mi = 0; mi < 4; mi++)
#pragma unroll
                    for (int nj = 0; nj < 4; nj++)
                        mma16816(acc[mi][nj], a[mi], b[nj]);
            }
        }
    }

    // ---------------- epilogue ----------------
    const int g = lane >> 2, q = lane & 3;
    if (MODE == 0) {
#pragma unroll
        for (int mi = 0; mi < 4; mi++) {
            int row0 = m0 + wm * 64 + mi * 16 + g;
            int row1 = row0 + 8;
#pragma unroll
            for (int nj = 0; nj < 4; nj++) {
                int col = n0 + wn * 32 + nj * 8 + 2 * q;
                float b0 = bias[col], b1 = bias[col + 1];
                float2 o0 = make_float2(acc[mi][nj][0] + b0, acc[mi][nj][1] + b1);
                float2 o1 = make_float2(acc[mi][nj][2] + b0, acc[mi][nj][3] + b1);
                *reinterpret_cast<float2*>(&C[(size_t)row0 * N + col]) = o0;
                *reinterpret_cast<float2*>(&C[(size_t)row1 * N + col]) = o1;
            }
        }
    } else {
        const int b = m0 >> 7;   // GM == S_
#pragma unroll
        for (int mi = 0; mi < 4; mi++) {
            float p0 = 0.f, p1 = 0.f;
#pragma unroll
            for (int nj = 0; nj < 4; nj++) {
                int col = n0 + wn * 32 + nj * 8 + 2 * q;
                float bz0 = bias[col], bz1 = bias[col + 1];
                float hv0 = hidden[b * H_ + col], hv1 = hidden[b * H_ + col + 1];
                p0 = fmaf(tanhf(acc[mi][nj][0] + bz0), hv0, p0);
                p0 = fmaf(tanhf(acc[mi][nj][1] + bz1), hv1, p0);
                p1 = fmaf(tanhf(acc[mi][nj][2] + bz0), hv0, p1);
                p1 = fmaf(tanhf(acc[mi][nj][3] + bz1), hv1, p1);
            }
            p0 += __shfl_xor_sync(0xffffffffu, p0, 1);
            p0 += __shfl_xor_sync(0xffffffffu, p0, 2);
            p1 += __shfl_xor_sync(0xffffffffu, p1, 1);
            p1 += __shfl_xor_sync(0xffffffffu, p1, 2);
            if (q == 0) {
                int row = m0 + wm * 64 + mi * 16 + g;
                atomicAdd(&scOut[row], p0);
                atomicAdd(&scOut[row + 8], p1);
            }
        }
    }
}

// ---------------- GRU ----------------
__global__ void gru_kernel(const float* __restrict__ prev,
                           float* __restrict__ outHidden) {
    int idx = blockIdx.x * blockDim.x + threadIdx.x;
    int b = idx >> 9, h = idx & (H_ - 1);
    const float* gi = g_gi + (size_t)b * G_;
    const float* gh = g_gh + (size_t)b * G_;
    float ir = gi[h], iz = gi[h + H_], inn = gi[h + 2 * H_];
    float hr = gh[h], hz = gh[h + H_], hn = gh[h + 2 * H_];
    float r = 1.f / (1.f + expf(-(ir + hr)));
    float z = 1.f / (1.f + expf(-(iz + hz)));
    float n = tanhf(inn + r * hn);
    float hv = (1.f - z) * n + z * prev[idx];
    g_hidden[idx] = hv;
    outHidden[idx] = hv;
}

// ---------------- softmax (online max+sum) ----------------
__global__ void __launch_bounds__(512)
softmax_kernel(float* __restrict__ pred, const int* __restrict__ src,
               const int* __restrict__ ids) {
    __shared__ float s_lc[S_];
    __shared__ float s_m[512];
    __shared__ float s_s[512];
    __shared__ int s_cnt;
    const int b = blockIdx.x, t = threadIdx.x;
    float* row = pred + (size_t)b * V_;

    if (t == 0) s_cnt = 0;
    if (t < S_) {
        float mask = (src[b * S_ + t] == 0) ? -1000.f : 0.f;
        s_lc[t] = tanhf(g_sc[b * S_ + t] + mask);
    }
    __syncthreads();

    float m = -1e30f, s = 0.f;
    for (int v = t; v < V_; v += 512) {
        float x = row[v];
        float nm = fmaxf(m, x);
        s = s * expf(m - nm) + expf(x - nm);
        m = nm;
    }
    if (t < S_) {
        float x = s_lc[t];
        float nm = fmaxf(m, x);
        s = s * expf(m - nm) + expf(x - nm);
        m = nm;
    }
    s_m[t] = m; s_s[t] = s;
    __syncthreads();
    for (int o = 256; o; o >>= 1) {
        if (t < o) {
            float m1 = s_m[t], m2 = s_m[t + o];
            float nm = fmaxf(m1, m2);
            s_s[t] = s_s[t] * expf(m1 - nm) + s_s[t + o] * expf(m2 - nm);
            s_m[t] = nm;
        }
        __syncthreads();
    }
    float gmax = s_m[0];
    float inv = 1.f / s_s[0];

    for (int v = t; v < V_; v += 512) row[v] = expf(row[v] - gmax) * inv;

    int id = ids[b];
    if (t < S_ && src[b * S_ + t] == id) atomicAdd(&s_cnt, 1);
    __syncthreads();

    if (t < S_) {
        float pc = expf(s_lc[t] - gmax) * inv;
        atomicAdd(&row[src[b * S_ + t]], pc);
        float eq = (src[b * S_ + t] == id) ? 1.f : 0.f;
        g_attn[b * S_ + t] = pc * eq / fmaxf((float)s_cnt, 1.f);
    }
}

__global__ void __launch_bounds__(256)
weighted_kernel(const float* __restrict__ enc, float* __restrict__ outW) {
    __shared__ float s_a[S_];
    const int b = blockIdx.x, t = threadIdx.x;
    if (t < S_) s_a[t] = g_attn[b * S_ + t];
    __syncthreads();
    float4 acc = make_float4(0.f, 0.f, 0.f, 0.f);
    const float4* e4 = reinterpret_cast<const float4*>(enc + (size_t)b * S_ * (2 * H_));
    for (int s = 0; s < S_; s++) {
        float w = s_a[s];
        if (w != 0.f) {
            float4 e = e4[s * 256 + t];
            acc.x = fmaf(w, e.x, acc.x); acc.y = fmaf(w, e.y, acc.y);
            acc.z = fmaf(w, e.z, acc.z); acc.w = fmaf(w, e.w, acc.w);
        }
    }
    reinterpret_cast<float4*>(outW)[b * 256 + t] = acc;
}

// ---------------- launch ----------------
extern "C" void kernel_launch(void* const* d_in, const int* in_sizes, int n_in,
                              void* d_out, int out_size) {
    const int*   input_ids = (const int*)d_in[0];
    const float* encoded   = (const float*)d_in[1];
    const int*   src       = (const int*)d_in[2];
    const float* prev      = (const float*)d_in[3];
    const float* weighted  = (const float*)d_in[4];
    const float* embed_w   = (const float*)d_in[6];
    const float* w_ih      = (const float*)d_in[7];
    const float* w_hh      = (const float*)d_in[8];
    const float* b_ih      = (const float*)d_in[9];
    const float* b_hh      = (const float*)d_in[10];
    const float* Wo_w      = (const float*)d_in[13];
    const float* Wo_b      = (const float*)d_in[14];
    const float* Wc_w      = (const float*)d_in[15];
    const float* Wc_b      = (const float*)d_in[16];

    float* pred        = (float*)d_out;
    float* outHidden   = pred + (size_t)B_ * V_;
    float* outWeighted = outHidden + (size_t)B_ * H_;

    float *px, *pgi, *pgh, *phid, *psc;
    cudaGetSymbolAddress((void**)&px,   g_x);
    cudaGetSymbolAddress((void**)&pgi,  g_gi);
    cudaGetSymbolAddress((void**)&pgh,  g_gh);
    cudaGetSymbolAddress((void**)&phid, g_hidden);
    cudaGetSymbolAddress((void**)&psc,  g_sc);

    cudaFuncSetAttribute(mma_gemm<0>, cudaFuncAttributeMaxDynamicSharedMemorySize, MMA_SMEM);
    cudaFuncSetAttribute(mma_gemm<1>, cudaFuncAttributeMaxDynamicSharedMemorySize, MMA_SMEM);

    // x = concat(embed[ids], weighted)
    build_x_kernel<<<(B_ * IN_) / 256, 256>>>(input_ids, embed_w, weighted);

    // gi = x @ W_ih^T + b_ih ; gh = prev @ W_hh^T + b_hh
    mma_gemm<0><<<dim3(G_ / GN, B_ / GM), 256, MMA_SMEM>>>(
        px, w_ih, b_ih, pgi, B_, G_, IN_, nullptr, nullptr);
    mma_gemm<0><<<dim3(G_ / GN, B_ / GM), 256, MMA_SMEM>>>(
        prev, w_hh, b_hh, pgh, B_, G_, H_, nullptr, nullptr);

    gru_kernel<<<(B_ * H_) / 256, 256>>>(prev, outHidden);

    // score_g = hidden @ Wo^T + Wo_b
    mma_gemm<0><<<dim3(V_ / GN, B_ / GM), 256, MMA_SMEM>>>(
        phid, Wo_w, Wo_b, pred, B_, V_, H_, nullptr, nullptr);

    // sc = einsum(tanh(enc @ Wc^T + Wc_b), hidden)
    zero_sc_kernel<<<(B_ * S_) / 256, 256>>>();
    mma_gemm<1><<<dim3(H_ / GN, (B_ * S_) / GM), 256, MMA_SMEM>>>(
        encoded, Wc_w, Wc_b, nullptr, B_ * S_, H_, 2 * H_, phid, psc);

    softmax_kernel<<<B_, 512>>>(pred, src, input_ids);
    weighted_kernel<<<B_, 256>>>(encoded, outWeighted);

    (void)in_sizes; (void)n_in; (void)out_size;
}